// round 1
// baseline (speedup 1.0000x reference)
#include <cuda_runtime.h>
#include <cstdint>

#define N_SEQ 512
#define N_RES 384
#define CM    256
#define CO    32
#define CZ    128
#define BC    12288          /* N_RES * CO */
#define LN_EPS 1e-5f
#define EPS    1e-3f

// ---------------- scratch (__device__ globals: alloc-free) ----------------
__device__ float g_L[N_SEQ * BC];                 // [a][b*32+c]  (25 MB)
__device__ float g_R[N_SEQ * BC];                 // [a][d*32+e]  (25 MB)
__device__ float g_inter[(size_t)BC * BC];        // [bc][de]     (604 MB)
__device__ float g_norm[N_RES * N_RES];           // [b][d]

// ---------------- helpers ----------------
__device__ __forceinline__ float rna_tf32(float x) {
    float y;
    asm("cvt.rna.tf32.f32 %0, %1;" : "=f"(y) : "f"(x));
    return y;
}

__device__ __forceinline__ void mma8(float d[4], const uint32_t a[4], const uint32_t b[2]) {
    asm volatile(
        "mma.sync.aligned.m16n8k8.row.col.f32.tf32.tf32.f32 "
        "{%0,%1,%2,%3}, {%4,%5,%6,%7}, {%8,%9}, {%0,%1,%2,%3};\n"
        : "+f"(d[0]), "+f"(d[1]), "+f"(d[2]), "+f"(d[3])
        : "r"(a[0]), "r"(a[1]), "r"(a[2]), "r"(a[3]),
          "r"(b[0]), "r"(b[1]));
}

// ---------------- K1: fused LayerNorm + left/right projection + mask ------
__global__ __launch_bounds__(128) void k_ln_proj(
    const float* __restrict__ act, const float* __restrict__ mask,
    const float* __restrict__ ln_s, const float* __restrict__ ln_o,
    const float* __restrict__ lw, const float* __restrict__ lb,
    const float* __restrict__ rw, const float* __restrict__ rb)
{
    int row = blockIdx.x;               // a*N_RES + b
    int t = threadIdx.x;                // 0..127
    __shared__ float an[CM];
    __shared__ float red[8];
    __shared__ float part[64];

    const float* x = act + (size_t)row * CM;
    float x0 = x[t], x1 = x[t + 128];
    float s = x0 + x1, ss = x0 * x0 + x1 * x1;
    #pragma unroll
    for (int o = 16; o; o >>= 1) {
        s  += __shfl_xor_sync(0xFFFFFFFFu, s, o);
        ss += __shfl_xor_sync(0xFFFFFFFFu, ss, o);
    }
    int w = t >> 5;
    if ((t & 31) == 0) { red[w] = s; red[4 + w] = ss; }
    __syncthreads();
    float st  = red[0] + red[1] + red[2] + red[3];
    float sst = red[4] + red[5] + red[6] + red[7];
    float mu = st * (1.0f / CM);
    float var = sst * (1.0f / CM) - mu * mu;
    float rstd = rsqrtf(var + LN_EPS);
    an[t]       = (x0 - mu) * rstd * ln_s[t]       + ln_o[t];
    an[t + 128] = (x1 - mu) * rstd * ln_s[t + 128] + ln_o[t + 128];
    __syncthreads();

    float m = mask[row];
    int c = t & 63;         // 0..63 : 0..31 left, 32..63 right
    int half = t >> 6;      // k-half split
    int cc = c & 31;
    const float* wp = ((c < 32) ? lw : rw) + cc;
    float acc = 0.f;
    int k0 = half * 128;
    #pragma unroll 8
    for (int k = k0; k < k0 + 128; k++)
        acc = fmaf(an[k], wp[k * CO], acc);

    if (half) part[c] = acc;
    __syncthreads();
    if (!half) {
        float tot = acc + part[c];
        float bia = (c < 32) ? lb[cc] : rb[cc];
        float v = rna_tf32(m * (tot + bia));
        float* dst = (c < 32) ? g_L : g_R;
        int a = row / N_RES, b = row % N_RES;
        dst[(size_t)a * BC + b * CO + cc] = v;
    }
}

// ---------------- K0: norm[b][d] = sum_a mask[a,b]*mask[a,d] --------------
__global__ __launch_bounds__(512) void k_norm(const float* __restrict__ mask)
{
    int b = blockIdx.x;
    __shared__ float mcol[N_SEQ];
    for (int a = threadIdx.x; a < N_SEQ; a += blockDim.x)
        mcol[a] = mask[a * N_RES + b];
    __syncthreads();
    for (int d = threadIdx.x; d < N_RES; d += blockDim.x) {
        float acc = 0.f;
        #pragma unroll 8
        for (int a = 0; a < N_SEQ; a++)
            acc = fmaf(mcol[a], mask[a * N_RES + d], acc);
        g_norm[b * N_RES + d] = acc;
    }
}

// ---------------- Stage A: inter[bc][de] = sum_a L[a][bc] * R[a][de] ------
// Block tile 64(m) x 128(n), K-tile 32, warps 2x4 each 32x32, tf32 mma.
__global__ __launch_bounds__(256) void k_outer()
{
    __shared__ float As[64][CO + 4];    // [m][k], pad 4 -> conflict-free frag reads
    __shared__ float Bs[32][128 + 8];   // [k][n], pad 8 -> conflict-free frag reads
    int m0 = blockIdx.y * 64;
    int n0 = blockIdx.x * 128;
    int tid = threadIdx.x;
    int warp = tid >> 5, lane = tid & 31;
    int wm = warp >> 2, wn = warp & 3;       // wm 0..1, wn 0..3
    int g = lane >> 2, tg = lane & 3;

    float acc[2][4][4] = {};

    int lm = tid & 63;          // As loader: m
    int lk = tid >> 6;          // As loader: k base (0..3)
    int bk = tid >> 5;          // Bs loader: k base (0..7)
    int bn4 = tid & 31;         // Bs loader: float4 col

    for (int kt = 0; kt < 16; kt++) {
        const float* lsrc = g_L + (size_t)(kt * 32) * BC + m0;
        #pragma unroll
        for (int j = 0; j < 8; j++)
            As[lm][lk + 4 * j] = lsrc[(size_t)(lk + 4 * j) * BC + lm];

        const float* rsrc = g_R + (size_t)(kt * 32) * BC + n0;
        #pragma unroll
        for (int j = 0; j < 4; j++) {
            float4 v = *(const float4*)(rsrc + (size_t)(bk + 8 * j) * BC + bn4 * 4);
            *(float4*)&Bs[bk + 8 * j][bn4 * 4] = v;
        }
        __syncthreads();

        #pragma unroll
        for (int ks = 0; ks < 4; ks++) {
            uint32_t afr[2][4], bfr[4][2];
            #pragma unroll
            for (int mi = 0; mi < 2; mi++) {
                int r = wm * 32 + mi * 16 + g;
                afr[mi][0] = __float_as_uint(As[r][ks * 8 + tg]);
                afr[mi][1] = __float_as_uint(As[r + 8][ks * 8 + tg]);
                afr[mi][2] = __float_as_uint(As[r][ks * 8 + tg + 4]);
                afr[mi][3] = __float_as_uint(As[r + 8][ks * 8 + tg + 4]);
            }
            #pragma unroll
            for (int ni = 0; ni < 4; ni++) {
                int cN = wn * 32 + ni * 8 + g;
                bfr[ni][0] = __float_as_uint(Bs[ks * 8 + tg][cN]);
                bfr[ni][1] = __float_as_uint(Bs[ks * 8 + tg + 4][cN]);
            }
            #pragma unroll
            for (int mi = 0; mi < 2; mi++)
                #pragma unroll
                for (int ni = 0; ni < 4; ni++)
                    mma8(acc[mi][ni], afr[mi], bfr[ni]);
        }
        __syncthreads();
    }

    // epilogue: tf32-round and store (stage B consumes as tf32 operands)
    #pragma unroll
    for (int mi = 0; mi < 2; mi++) {
        int r0 = m0 + wm * 32 + mi * 16 + g;
        #pragma unroll
        for (int ni = 0; ni < 4; ni++) {
            int cN = n0 + wn * 32 + ni * 8 + 2 * tg;
            float2 v;
            v.x = rna_tf32(acc[mi][ni][0]); v.y = rna_tf32(acc[mi][ni][1]);
            *(float2*)&g_inter[(size_t)r0 * BC + cN] = v;
            v.x = rna_tf32(acc[mi][ni][2]); v.y = rna_tf32(acc[mi][ni][3]);
            *(float2*)&g_inter[(size_t)(r0 + 8) * BC + cN] = v;
        }
    }
}

// ---------------- Stage B: out[b][d][f] = inter[b,:,d,:] . W + bias, /norm
// Per block: one b, 64 d's, all 128 f. K = 1024 = 32 chunks of (c fixed, e=0..31).
__global__ __launch_bounds__(256) void k_proj_out(
    const float* __restrict__ Wg, const float* __restrict__ ob,
    float* __restrict__ out)
{
    __shared__ float As[64][CO + 4];    // [d][e]
    __shared__ float Ws[32][128 + 8];   // [e][f]
    int b  = blockIdx.y;
    int d0 = blockIdx.x * 64;
    int tid = threadIdx.x;
    int warp = tid >> 5, lane = tid & 31;
    int wm = warp >> 2, wn = warp & 3;
    int g = lane >> 2, tg = lane & 3;

    float acc[2][4][4] = {};

    for (int c = 0; c < 32; c++) {
        // A tile: 2048 contiguous floats from inter row (b*32+c), col d0*32
        const float4* src = (const float4*)(g_inter + (size_t)(b * 32 + c) * BC + (size_t)d0 * 32);
        #pragma unroll
        for (int j = 0; j < 2; j++) {
            int idx = tid + 256 * j;            // 0..511
            int d = idx >> 3, e4 = idx & 7;
            float4 v = src[idx];
            *(float4*)&As[d][e4 * 4] = v;
        }
        // W tile: rows c*32 .. c*32+31, 128 f each; tf32-round on the fly
        const float4* wsrc = (const float4*)(Wg + (size_t)c * 32 * CZ);
        #pragma unroll
        for (int j = 0; j < 4; j++) {
            int idx = tid + 256 * j;            // 0..1023
            int e = idx >> 5, f4 = idx & 31;
            float4 v = wsrc[idx];
            v.x = rna_tf32(v.x); v.y = rna_tf32(v.y);
            v.z = rna_tf32(v.z); v.w = rna_tf32(v.w);
            *(float4*)&Ws[e][f4 * 4] = v;
        }
        __syncthreads();

        #pragma unroll
        for (int ks = 0; ks < 4; ks++) {
            uint32_t afr[2][4], bfr[4][2];
            #pragma unroll
            for (int mi = 0; mi < 2; mi++) {
                int r = wm * 32 + mi * 16 + g;
                afr[mi][0] = __float_as_uint(As[r][ks * 8 + tg]);
                afr[mi][1] = __float_as_uint(As[r + 8][ks * 8 + tg]);
                afr[mi][2] = __float_as_uint(As[r][ks * 8 + tg + 4]);
                afr[mi][3] = __float_as_uint(As[r + 8][ks * 8 + tg + 4]);
            }
            #pragma unroll
            for (int ni = 0; ni < 4; ni++) {
                int cN = wn * 32 + ni * 8 + g;
                bfr[ni][0] = __float_as_uint(Ws[ks * 8 + tg][cN]);
                bfr[ni][1] = __float_as_uint(Ws[ks * 8 + tg + 4][cN]);
            }
            #pragma unroll
            for (int mi = 0; mi < 2; mi++)
                #pragma unroll
                for (int ni = 0; ni < 4; ni++)
                    mma8(acc[mi][ni], afr[mi], bfr[ni]);
        }
        __syncthreads();
    }

    // epilogue: + output_b, / (EPS + norm[b,d])
    #pragma unroll
    for (int mi = 0; mi < 2; mi++) {
        int dl = wm * 32 + mi * 16 + g;
        float inv0 = 1.0f / (EPS + g_norm[b * N_RES + d0 + dl]);
        float inv1 = 1.0f / (EPS + g_norm[b * N_RES + d0 + dl + 8]);
        #pragma unroll
        for (int ni = 0; ni < 4; ni++) {
            int f = wn * 32 + ni * 8 + 2 * tg;
            float b0 = ob[f], b1 = ob[f + 1];
            size_t o0 = ((size_t)b * N_RES + d0 + dl) * CZ + f;
            float2 v;
            v.x = (acc[mi][ni][0] + b0) * inv0;
            v.y = (acc[mi][ni][1] + b1) * inv0;
            *(float2*)&out[o0] = v;
            v.x = (acc[mi][ni][2] + b0) * inv1;
            v.y = (acc[mi][ni][3] + b1) * inv1;
            *(float2*)&out[o0 + (size_t)8 * CZ] = v;
        }
    }
}

// ---------------- launch ----------------
extern "C" void kernel_launch(void* const* d_in, const int* in_sizes, int n_in,
                              void* d_out, int out_size)
{
    const float* act  = (const float*)d_in[0];
    const float* mask = (const float*)d_in[1];
    const float* ln_s = (const float*)d_in[2];
    const float* ln_o = (const float*)d_in[3];
    const float* lw   = (const float*)d_in[4];
    const float* lb   = (const float*)d_in[5];
    const float* rw   = (const float*)d_in[6];
    const float* rb   = (const float*)d_in[7];
    const float* ow   = (const float*)d_in[8];
    const float* ob   = (const float*)d_in[9];
    float* out = (float*)d_out;

    k_ln_proj<<<N_SEQ * N_RES, 128>>>(act, mask, ln_s, ln_o, lw, lb, rw, rb);
    k_norm<<<N_RES, 512>>>(mask);
    k_outer<<<dim3(BC / 128, BC / 64), 256>>>();
    k_proj_out<<<dim3(N_RES / 64, N_RES), 256>>>(ow, ob, out);
}

// round 3
// speedup vs baseline: 1.0886x; 1.0886x over previous
#include <cuda_runtime.h>
#include <cstdint>

#define N_SEQ 512
#define N_RES 384
#define CM    256
#define CO    32
#define CZ    128
#define BC    12288          /* N_RES * CO */
#define LN_EPS 1e-5f
#define EPS    1e-3f

// ---------------- scratch (__device__ globals: alloc-free) ----------------
__device__ float g_L[(size_t)BC * N_SEQ];      // [bc][a]  K-major  (25 MB)
__device__ float g_R[(size_t)BC * N_SEQ];      // [de][a]  K-major  (25 MB)
__device__ float g_inter[(size_t)BC * BC];     // [bc][de]          (604 MB)
__device__ float g_norm[N_RES * N_RES];        // [b][d]
__device__ float g_Wt[CO * CZ * CO];           // [c][f][e]

// ---------------- helpers ----------------
__device__ __forceinline__ float rna_tf32(float x) {
    float y;
    asm("cvt.rna.tf32.f32 %0, %1;" : "=f"(y) : "f"(x));
    return y;
}
__device__ __forceinline__ void mma8(float d[4], const uint32_t a[4], const uint32_t b[2]) {
    asm volatile(
        "mma.sync.aligned.m16n8k8.row.col.f32.tf32.tf32.f32 "
        "{%0,%1,%2,%3}, {%4,%5,%6,%7}, {%8,%9}, {%0,%1,%2,%3};\n"
        : "+f"(d[0]), "+f"(d[1]), "+f"(d[2]), "+f"(d[3])
        : "r"(a[0]), "r"(a[1]), "r"(a[2]), "r"(a[3]),
          "r"(b[0]), "r"(b[1]));
}
__device__ __forceinline__ void cpa16(uint32_t dst, const void* src) {
    asm volatile("cp.async.cg.shared.global [%0], [%1], 16;" :: "r"(dst), "l"(src));
}
#define CP_COMMIT() asm volatile("cp.async.commit_group;" ::: "memory")
#define CP_WAIT1()  asm volatile("cp.async.wait_group 1;" ::: "memory")

// ---------------- K1: fused LayerNorm + left/right projection + mask ------
__global__ __launch_bounds__(128) void k_ln_proj(
    const float* __restrict__ act, const float* __restrict__ mask,
    const float* __restrict__ ln_s, const float* __restrict__ ln_o,
    const float* __restrict__ lw, const float* __restrict__ lb,
    const float* __restrict__ rw, const float* __restrict__ rb)
{
    int row = blockIdx.x;               // a*N_RES + b
    int t = threadIdx.x;
    __shared__ float an[CM];
    __shared__ float red[8];
    __shared__ float part[64];

    const float* x = act + (size_t)row * CM;
    float x0 = x[t], x1 = x[t + 128];
    float s = x0 + x1, ss = x0 * x0 + x1 * x1;
    #pragma unroll
    for (int o = 16; o; o >>= 1) {
        s  += __shfl_xor_sync(0xFFFFFFFFu, s, o);
        ss += __shfl_xor_sync(0xFFFFFFFFu, ss, o);
    }
    int w = t >> 5;
    if ((t & 31) == 0) { red[w] = s; red[4 + w] = ss; }
    __syncthreads();
    float st  = red[0] + red[1] + red[2] + red[3];
    float sst = red[4] + red[5] + red[6] + red[7];
    float mu = st * (1.0f / CM);
    float var = sst * (1.0f / CM) - mu * mu;
    float rstd = rsqrtf(var + LN_EPS);
    an[t]       = (x0 - mu) * rstd * ln_s[t]       + ln_o[t];
    an[t + 128] = (x1 - mu) * rstd * ln_s[t + 128] + ln_o[t + 128];
    __syncthreads();

    float m = mask[row];
    int c = t & 63;
    int half = t >> 6;
    int cc = c & 31;
    const float* wp = ((c < 32) ? lw : rw) + cc;
    float acc = 0.f;
    int k0 = half * 128;
    #pragma unroll 8
    for (int k = k0; k < k0 + 128; k++)
        acc = fmaf(an[k], wp[k * CO], acc);

    if (half) part[c] = acc;
    __syncthreads();
    if (!half) {
        float tot = acc + part[c];
        float bia = (c < 32) ? lb[cc] : rb[cc];
        float v = rna_tf32(m * (tot + bia));
        float* dst = (c < 32) ? g_L : g_R;
        int a = row / N_RES, b = row % N_RES;
        dst[(size_t)(b * CO + cc) * N_SEQ + a] = v;   // K-major [bc][a]
    }
}

// ---------------- K0: norm[b][d] = sum_a mask[a,b]*mask[a,d] --------------
__global__ __launch_bounds__(512) void k_norm(const float* __restrict__ mask)
{
    int b = blockIdx.x;
    __shared__ float mcol[N_SEQ];
    for (int a = threadIdx.x; a < N_SEQ; a += blockDim.x)
        mcol[a] = mask[a * N_RES + b];
    __syncthreads();
    for (int d = threadIdx.x; d < N_RES; d += blockDim.x) {
        float acc = 0.f;
        #pragma unroll 8
        for (int a = 0; a < N_SEQ; a++)
            acc = fmaf(mcol[a], mask[a * N_RES + d], acc);
        g_norm[b * N_RES + d] = acc;
    }
}

// ---------------- W transpose: Wt[c][f][e] = W[c][e][f] -------------------
__global__ __launch_bounds__(256) void k_tw(const float* __restrict__ W)
{
    int c = blockIdx.x;
    for (int i = threadIdx.x; i < CZ * CO; i += 256) {
        int f = i >> 5, e = i & 31;
        g_Wt[c * CZ * CO + i] = rna_tf32(W[c * CO * CZ + e * CZ + f]);
    }
}

// ---------------- Stage A: inter = L^T R, tile 128m x 256n, BK=32 ---------
// 8 warps (2x4), warp tile 64x64, cp.async double buffer.
#define A_ROWSZ 36
#define SA_A (128 * A_ROWSZ)             /* floats per A buffer */
#define SA_B (256 * A_ROWSZ)
#define SA_TOTAL ((2 * SA_A + 2 * SA_B) * 4)

__global__ __launch_bounds__(256, 1) void k_outer_mma()
{
    extern __shared__ __align__(128) float sm[];
    float* As[2] = { sm, sm + SA_A };
    float* Bs[2] = { sm + 2 * SA_A, sm + 2 * SA_A + SA_B };

    int tid = threadIdx.x;
    int m0 = blockIdx.y * 128;
    int n0 = blockIdx.x * 256;
    int warp = tid >> 5, lane = tid & 31;
    int wm = warp >> 2, wn = warp & 3;      // 2 x 4
    int g = lane >> 2, tg = lane & 3;

    float acc[4][8][4] = {};

    int r8 = tid >> 3, q = tid & 7;         // loader coords

    // prefetch kt=0,1
    #pragma unroll
    for (int kt = 0; kt < 2; kt++) {
        const float* asrc = g_L + (size_t)(m0 + r8) * N_SEQ + kt * 32 + q * 4;
        #pragma unroll
        for (int j = 0; j < 4; j++)
            cpa16((uint32_t)__cvta_generic_to_shared(&As[kt][(r8 + 32 * j) * A_ROWSZ + q * 4]),
                  asrc + (size_t)(32 * j) * N_SEQ);
        const float* bsrc = g_R + (size_t)(n0 + r8) * N_SEQ + kt * 32 + q * 4;
        #pragma unroll
        for (int j = 0; j < 8; j++)
            cpa16((uint32_t)__cvta_generic_to_shared(&Bs[kt][(r8 + 32 * j) * A_ROWSZ + q * 4]),
                  bsrc + (size_t)(32 * j) * N_SEQ);
        CP_COMMIT();
    }

    for (int kt = 0; kt < 16; kt++) {
        CP_WAIT1();
        __syncthreads();
        int buf = kt & 1;
        const float* Ab = As[buf];
        const float* Bb = Bs[buf];
        #pragma unroll
        for (int k8 = 0; k8 < 4; k8++) {
            int kk = k8 * 8 + tg;
            uint32_t af[4][4], bf[8][2];
            #pragma unroll
            for (int mi = 0; mi < 4; mi++) {
                int r = (wm * 64 + mi * 16 + g) * A_ROWSZ;
                af[mi][0] = __float_as_uint(Ab[r + kk]);
                af[mi][1] = __float_as_uint(Ab[r + 8 * A_ROWSZ + kk]);
                af[mi][2] = __float_as_uint(Ab[r + kk + 4]);
                af[mi][3] = __float_as_uint(Ab[r + 8 * A_ROWSZ + kk + 4]);
            }
            #pragma unroll
            for (int ni = 0; ni < 8; ni++) {
                int r = (wn * 64 + ni * 8 + g) * A_ROWSZ;
                bf[ni][0] = __float_as_uint(Bb[r + kk]);
                bf[ni][1] = __float_as_uint(Bb[r + kk + 4]);
            }
            #pragma unroll
            for (int mi = 0; mi < 4; mi++)
                #pragma unroll
                for (int ni = 0; ni < 8; ni++)
                    mma8(acc[mi][ni], af[mi], bf[ni]);
        }
        __syncthreads();
        if (kt + 2 < 16) {
            const float* asrc = g_L + (size_t)(m0 + r8) * N_SEQ + (kt + 2) * 32 + q * 4;
            #pragma unroll
            for (int j = 0; j < 4; j++)
                cpa16((uint32_t)__cvta_generic_to_shared(&As[buf][(r8 + 32 * j) * A_ROWSZ + q * 4]),
                      asrc + (size_t)(32 * j) * N_SEQ);
            const float* bsrc = g_R + (size_t)(n0 + r8) * N_SEQ + (kt + 2) * 32 + q * 4;
            #pragma unroll
            for (int j = 0; j < 8; j++)
                cpa16((uint32_t)__cvta_generic_to_shared(&Bs[buf][(r8 + 32 * j) * A_ROWSZ + q * 4]),
                      bsrc + (size_t)(32 * j) * N_SEQ);
        }
        CP_COMMIT();
    }

    // epilogue: tf32-round and store
    #pragma unroll
    for (int mi = 0; mi < 4; mi++) {
        size_t r0 = (size_t)(m0 + wm * 64 + mi * 16 + g) * BC;
        #pragma unroll
        for (int ni = 0; ni < 8; ni++) {
            int cN = n0 + wn * 64 + ni * 8 + 2 * tg;
            float2 v;
            v.x = rna_tf32(acc[mi][ni][0]); v.y = rna_tf32(acc[mi][ni][1]);
            *(float2*)&g_inter[r0 + cN] = v;
            v.x = rna_tf32(acc[mi][ni][2]); v.y = rna_tf32(acc[mi][ni][3]);
            *(float2*)&g_inter[r0 + (size_t)8 * BC + cN] = v;
        }
    }
}

// ---------------- Stage B: out[b][d][f], tile 128d x 128f, K=1024 ---------
// 4 warps (2x2), warp tile 64x64, cp.async double buffer. ktile = one c.
#define SB_A (128 * A_ROWSZ)
#define SB_B (128 * A_ROWSZ)
#define SB_TOTAL ((2 * SB_A + 2 * SB_B) * 4)

__global__ __launch_bounds__(128, 2) void k_proj_mma(
    const float* __restrict__ ob, float* __restrict__ out)
{
    extern __shared__ __align__(128) float sm[];
    float* As[2] = { sm, sm + SB_A };
    float* Bs[2] = { sm + 2 * SB_A, sm + 2 * SB_A + SB_B };

    int tid = threadIdx.x;
    int b  = blockIdx.y;
    int d0 = blockIdx.x * 128;
    int warp = tid >> 5, lane = tid & 31;
    int wm = warp >> 1, wn = warp & 1;      // 2 x 2
    int g = lane >> 2, tg = lane & 3;

    float acc[4][8][4] = {};

    int r8 = tid >> 3, q = tid & 7;

    #pragma unroll
    for (int c = 0; c < 2; c++) {
        const float* asrc = g_inter + (size_t)(b * CO + c) * BC + (size_t)(d0 + r8) * 32 + q * 4;
        #pragma unroll
        for (int j = 0; j < 8; j++)
            cpa16((uint32_t)__cvta_generic_to_shared(&As[c][(r8 + 16 * j) * A_ROWSZ + q * 4]),
                  asrc + (size_t)(16 * j) * 32);
        const float* bsrc = g_Wt + c * CZ * CO + r8 * 32 + q * 4;
        #pragma unroll
        for (int j = 0; j < 8; j++)
            cpa16((uint32_t)__cvta_generic_to_shared(&Bs[c][(r8 + 16 * j) * A_ROWSZ + q * 4]),
                  bsrc + (size_t)(16 * j) * 32);
        CP_COMMIT();
    }

    for (int c = 0; c < 32; c++) {
        CP_WAIT1();
        __syncthreads();
        int buf = c & 1;
        const float* Ab = As[buf];
        const float* Bb = Bs[buf];
        #pragma unroll
        for (int k8 = 0; k8 < 4; k8++) {
            int kk = k8 * 8 + tg;
            uint32_t af[4][4], bf[8][2];
            #pragma unroll
            for (int mi = 0; mi < 4; mi++) {
                int r = (wm * 64 + mi * 16 + g) * A_ROWSZ;
                af[mi][0] = __float_as_uint(Ab[r + kk]);
                af[mi][1] = __float_as_uint(Ab[r + 8 * A_ROWSZ + kk]);
                af[mi][2] = __float_as_uint(Ab[r + kk + 4]);
                af[mi][3] = __float_as_uint(Ab[r + 8 * A_ROWSZ + kk + 4]);
            }
            #pragma unroll
            for (int ni = 0; ni < 8; ni++) {
                int r = (wn * 64 + ni * 8 + g) * A_ROWSZ;
                bf[ni][0] = __float_as_uint(Bb[r + kk]);
                bf[ni][1] = __float_as_uint(Bb[r + kk + 4]);
            }
            #pragma unroll
            for (int mi = 0; mi < 4; mi++)
                #pragma unroll
                for (int ni = 0; ni < 8; ni++)
                    mma8(acc[mi][ni], af[mi], bf[ni]);
        }
        __syncthreads();
        if (c + 2 < 32) {
            const float* asrc = g_inter + (size_t)(b * CO + c + 2) * BC + (size_t)(d0 + r8) * 32 + q * 4;
            #pragma unroll
            for (int j = 0; j < 8; j++)
                cpa16((uint32_t)__cvta_generic_to_shared(&As[buf][(r8 + 16 * j) * A_ROWSZ + q * 4]),
                      asrc + (size_t)(16 * j) * 32);
            const float* bsrc = g_Wt + (c + 2) * CZ * CO + r8 * 32 + q * 4;
            #pragma unroll
            for (int j = 0; j < 8; j++)
                cpa16((uint32_t)__cvta_generic_to_shared(&Bs[buf][(r8 + 16 * j) * A_ROWSZ + q * 4]),
                      bsrc + (size_t)(16 * j) * 32);
        }
        CP_COMMIT();
    }

    // epilogue: + bias, / (EPS + norm)
    #pragma unroll
    for (int mi = 0; mi < 4; mi++) {
        int dl = wm * 64 + mi * 16 + g;
        float inv0 = 1.0f / (EPS + g_norm[b * N_RES + d0 + dl]);
        float inv1 = 1.0f / (EPS + g_norm[b * N_RES + d0 + dl + 8]);
        size_t o0 = ((size_t)b * N_RES + d0 + dl) * CZ;
        #pragma unroll
        for (int ni = 0; ni < 8; ni++) {
            int f = wn * 64 + ni * 8 + 2 * tg;
            float b0 = ob[f], b1 = ob[f + 1];
            float2 v;
            v.x = (acc[mi][ni][0] + b0) * inv0;
            v.y = (acc[mi][ni][1] + b1) * inv0;
            *(float2*)&out[o0 + f] = v;
            v.x = (acc[mi][ni][2] + b0) * inv1;
            v.y = (acc[mi][ni][3] + b1) * inv1;
            *(float2*)&out[o0 + (size_t)8 * CZ + f] = v;
        }
    }
}

// ---------------- launch ----------------
extern "C" void kernel_launch(void* const* d_in, const int* in_sizes, int n_in,
                              void* d_out, int out_size)
{
    const float* act  = (const float*)d_in[0];
    const float* mask = (const float*)d_in[1];
    const float* ln_s = (const float*)d_in[2];
    const float* ln_o = (const float*)d_in[3];
    const float* lw   = (const float*)d_in[4];
    const float* lb   = (const float*)d_in[5];
    const float* rw   = (const float*)d_in[6];
    const float* rb   = (const float*)d_in[7];
    const float* ow   = (const float*)d_in[8];
    const float* ob   = (const float*)d_in[9];
    float* out = (float*)d_out;

    static int once = 0;
    if (!once) {
        cudaFuncSetAttribute(k_outer_mma, cudaFuncAttributeMaxDynamicSharedMemorySize, SA_TOTAL);
        cudaFuncSetAttribute(k_proj_mma,  cudaFuncAttributeMaxDynamicSharedMemorySize, SB_TOTAL);
        once = 1;
    }

    k_ln_proj<<<N_SEQ * N_RES, 128>>>(act, mask, ln_s, ln_o, lw, lb, rw, rb);
    k_norm<<<N_RES, 512>>>(mask);
    k_tw<<<CO, 256>>>(ow);
    k_outer_mma<<<dim3(BC / 256, BC / 128), 256, SA_TOTAL>>>();
    k_proj_mma<<<dim3(N_RES / 128, N_RES), 128, SB_TOTAL>>>(ob, out);
}